// round 11
// baseline (speedup 1.0000x reference)
#include <cuda_runtime.h>
#include <math.h>

#define KK 769
#define MM 384
#define BB 64
#define LL 256
#define AA 21
#define ESTR 772
#define NT 64
#define TE 6
#define NEGV (-1.0e32f)

__device__ __align__(16) float g_eobs[(AA + 1) * ESTR];
__device__ float g_cm[KK];
__device__ float g_ci[KK];
__device__ float g_cf[KK];
__device__ float g_et[KK];
__device__ float g_w[MM];
__device__ float g_einit[KK];

// ---------------- emission table (parallel, independent of prep) ----------------
__global__ __launch_bounds__(128) void emis_kernel(
    const float* __restrict__ pre, const float* __restrict__ iseq)
{
    const int k = blockIdx.x * 128 + threadIdx.x;
    if (k >= KK) return;
    const float* row = (k < MM) ? (pre + k * AA) : (iseq + (k - MM) * AA);
    float mx = -INFINITY;
    #pragma unroll
    for (int a = 0; a < AA; a++) mx = fmaxf(mx, row[a]);
    float sm = 0.f;
    #pragma unroll
    for (int a = 0; a < AA; a++) sm += __expf(row[a] - mx);
    float l = mx + __logf(sm);
    float sm2 = 0.f;
    #pragma unroll
    for (int a = 0; a < AA; a++) sm2 += __expf(row[a] - l);
    float nrm = l + __logf(sm2);
    #pragma unroll
    for (int a = 0; a < AA; a++) g_eobs[a * ESTR + k] = __expf(row[a] - nrm);
    g_eobs[AA * ESTR + k] = 1.0f;
}

// ---------------- prep: transition constants + init ----------------
__global__ __launch_bounds__(512) void prep_kernel(
    const float* __restrict__ ins, const float* __restrict__ del)
{
    __shared__ float lre[(MM + 1) * 6], lue[(MM + 1) * 6];
    __shared__ float sC[MM + 2], sW2[MM + 1], sQt[MM + 1], sG[MM + 1];
    __shared__ float WT[16], ST[16], FIN[16], red[16];
    __shared__ float sInit[KK];

    const int tid = threadIdx.x, lane = tid & 31, wid = tid >> 5;

    for (int idx = tid; idx < MM * 3; idx += 512) {
        float x0 = ins[idx * 2], x1 = ins[idx * 2 + 1];
        float mx = fmaxf(x0, x1);
        float l = mx + __logf(__expf(x0 - mx) + __expf(x1 - mx));
        lre[idx * 2] = x0 - l; lre[idx * 2 + 1] = x1 - l;
        x0 = del[idx * 2]; x1 = del[idx * 2 + 1];
        mx = fmaxf(x0, x1);
        l = mx + __logf(__expf(x0 - mx) + __expf(x1 - mx));
        lue[idx * 2] = x0 - l; lue[idx * 2 + 1] = x1 - l;
    }
    if (tid < 3) {
        lre[(MM * 3 + tid) * 2 + 0] = NEGV; lre[(MM * 3 + tid) * 2 + 1] = 0.f;
        lue[(MM * 3 + tid) * 2 + 0] = 0.f;  lue[(MM * 3 + tid) * 2 + 1] = NEGV;
    }
    __syncthreads();

    { // C (exclusive cumsum of d2), w2, Qt
        float d2 = 0.f;
        if (tid < MM) d2 = lre[(tid * 3 + 2) * 2 + 0] + lue[(tid * 3 + 2) * 2 + 1];
        float inc = d2;
        #pragma unroll
        for (int o = 1; o < 32; o <<= 1) {
            float t = __shfl_up_sync(0xffffffffu, inc, o);
            if (lane >= o) inc += t;
        }
        if (lane == 31) WT[wid] = inc;
        __syncthreads();
        float off = 0.f;
        for (int j = 0; j < wid; j++) off += WT[j];
        if (tid < MM) { sC[tid + 1] = inc + off; sW2[tid] = __expf(d2); }
        if (tid == 0) { sC[0] = 0.f; sC[MM + 1] = 0.f; sW2[MM] = 0.f; }
        if (tid <= MM) {
            float q = __expf(lre[(tid * 3 + 2) * 2 + 1]);
            if (tid < MM) q += __expf(lre[(tid * 3 + 2) * 2 + 0] + lue[(tid * 3 + 2) * 2 + 0]);
            sQt[tid] = q;
        }
        __syncthreads();
    }
    { // G via reverse affine scan
        float A = 1.f, Bv = 0.f;
        if (tid < MM) { A = sW2[MM - tid]; Bv = sQt[MM - tid]; }
        #pragma unroll
        for (int o = 1; o < 32; o <<= 1) {
            float Wp = __shfl_up_sync(0xffffffffu, A, o);
            float Sp = __shfl_up_sync(0xffffffffu, Bv, o);
            if (lane >= o) { Bv = fmaf(A, Sp, Bv); A *= Wp; }
        }
        if (lane == 31 && wid < 12) { WT[wid] = A; ST[wid] = Bv; }
        __syncthreads();
        if (wid == 0) {
            float Wt = (lane < 12) ? WT[lane] : 1.f;
            float St = (lane < 12) ? ST[lane] : 0.f;
            #pragma unroll
            for (int o = 1; o < 16; o <<= 1) {
                float Wp = __shfl_up_sync(0xffffffffu, Wt, o);
                float Sp = __shfl_up_sync(0xffffffffu, St, o);
                if (lane >= o) { St = fmaf(Wt, Sp, St); Wt *= Wp; }
            }
            float e = __shfl_up_sync(0xffffffffu, St, 1);
            if (lane == 0) e = 0.f;
            if (lane < 12) FIN[lane] = e;
        }
        __syncthreads();
        if (tid < MM) sG[MM - 1 - tid] = fmaf(A, FIN[wid], Bv);
        if (tid == 0) sG[MM] = 0.f;
        __syncthreads();
    }
    for (int k = tid; k < KK; k += 512) {
        const int m = (k < MM) ? k : k - MM;
        const int g = (k < MM) ? 0 : 1;
        const int s = m + 1 - g;
        float src_stay  = lre[(s * 3 + g) * 2 + 0];
        float src_ins   = lre[(s * 3 + g) * 2 + 1];
        float src_match = lue[(s * 3 + g) * 2 + 0];
        float src_del   = lue[(s * 3 + g) * 2 + 1];
        float dmatch = src_stay + src_match, dins = src_ins, cflog = src_stay + src_del;
        float rowsum = __expf(dins) + ((s < MM) ? __expf(dmatch) : 0.f) + __expf(cflog) * sG[s];
        float lse = __logf(rowsum);
        g_cm[k] = __expf(dmatch - lse);
        g_ci[k] = __expf(dins - lse);
        g_cf[k] = __expf(cflog - lse);
        float tterm = (g == 1) ? lre[(m * 3 + 2) * 2 + 1]
                               : (lre[(m * 3 + 2) * 2 + 0] + lue[(m * 3 + 2) * 2 + 0]);
        g_et[k] = __expf(tterm);
        float initv;
        if (m == 0) initv = (g == 1) ? lre[1] : (lre[0] + lue[0]);
        else        initv = lre[0] + lue[1] - sC[1] + sC[m] + tterm;
        sInit[k] = initv;
    }
    if (tid < MM) g_w[tid] = sW2[tid];
    __syncthreads();
    { // normalized exp(init)
        float mloc = -INFINITY;
        for (int k = tid; k < KK; k += 512) mloc = fmaxf(mloc, sInit[k]);
        #pragma unroll
        for (int o = 16; o; o >>= 1) mloc = fmaxf(mloc, __shfl_xor_sync(0xffffffffu, mloc, o));
        if (lane == 0) red[wid] = mloc;
        __syncthreads();
        float mxI = red[0];
        #pragma unroll
        for (int j = 1; j < 16; j++) mxI = fmaxf(mxI, red[j]);
        __syncthreads();
        float s0 = 0.f;
        for (int k = tid; k < KK; k += 512) s0 += __expf(sInit[k] - mxI);
        #pragma unroll
        for (int o = 16; o; o >>= 1) s0 += __shfl_xor_sync(0xffffffffu, s0, o);
        if (lane == 0) red[wid] = s0;
        __syncthreads();
        float Z = 0.f;
        for (int j = 0; j < 16; j++) Z += red[j];
        float lz = mxI + __logf(Z);
        for (int k = tid; k < KK; k += 512) g_einit[k] = __expf(sInit[k] - lz);
    }
}

// ---------------- one forward step: 2 warps x 6 elems, ONE barrier ----------------
template <bool RESC, int P>
__device__ __forceinline__ void stepfn(
    const float (&um)[TE], const float (&ui)[TE], float uxin,
    float (&vm)[TE], float (&vi)[TE], float& vx,
    const float (&w_)[TE], const float (&cfa)[TE], const float (&cfb)[TE],
    const float (&cma)[TE], const float (&cmb)[TE],
    const float (&cia)[TE], const float (&cib)[TE],
    const float (&etm)[TE], const float (&eti)[TE],
    const float (&WL)[5], float Wexcl, float kw1,
    float4* s_T, float* s_bnd,
    int j0, int lane, int wid, bool l63,
    float et_x, float ci_xa, float ci_xb,
    const float* __restrict__ ob, int& pacc)
{
    // emission loads (issued early, L1-resident)
    float em[TE], ei[TE];
    #pragma unroll
    for (int q = 0; q < TE; q++) { em[q] = ob[j0 + q]; ei[q] = ob[MM + j0 + q]; }
    float e_x = l63 ? ob[KK - 1] : 0.f;

    // intra-warp boundary (valid for lanes >= 1)
    float ubm1 = __shfl_up_sync(0xffffffffu, um[TE - 1], 1);
    float ub_s = lane ? ubm1 : 0.f;

    // sources (warp1 lane0's first source partial; B-term injected via kw1)
    float Sr[TE];
    Sr[0] = fmaf(ub_s, cfb[0], ui[0] * cfa[0]);
    #pragma unroll
    for (int q = 1; q < TE; q++)
        Sr[q] = fmaf(um[q - 1], cfb[q], ui[q] * cfa[q]);
    float Sv = Sr[0];
    #pragma unroll
    for (int q = 1; q < TE; q++) Sv = fmaf(w_[q], Sv, Sr[q]);

    // S-only inclusive affine scan (constant W multipliers)
    #pragma unroll
    for (int k = 0; k < 5; k++) {
        const int o = 1 << k;
        float Sp = __shfl_up_sync(0xffffffffu, Sv, o);
        if (lane >= o) Sv = fmaf(WL[k], Sp, Sv);
    }

    float zs = 0.f;
    if (RESC) {
        zs = uxin;
        #pragma unroll
        for (int q = 0; q < TE; q++) zs += um[q] + ui[q];
        #pragma unroll
        for (int o = 16; o; o >>= 1) zs += __shfl_xor_sync(0xffffffffu, zs, o);
    }
    // exclusive-shift shfl issued before barrier (off the post-bar path)
    float Sp1 = __shfl_up_sync(0xffffffffu, Sv, 1);
    if (lane == 31) {
        if (wid == 0) { s_T[P].x = Sv; s_T[P].y = zs; }
        else          { s_T[P].z = Sv; s_T[P].w = zs; }
    }
    __syncthreads();

    // phase 2: one LDS.128 gets both warps' totals
    float4 T = s_T[P];
    float rz = 1.f;
    if (RESC) {
        float Tz = T.y + T.w;
        unsigned ze = (__float_as_uint(Tz) >> 23) & 255u;
        pacc += (int)ze - 127;
        rz = __uint_as_float((254u - ze) << 23);
    }
    const float bv = s_bnd[P];
    const float bc1 = bv * kw1;
    float Fin = wid ? (T.x + bc1) : 0.f;

    float Fexp = lane ? fmaf(Wexcl, Fin, Sp1) : Fin;
    float F0  = lane ? Fexp : (wid ? (Fexp - bc1) : Fexp);
    float ub0 = lane ? ubm1 : (wid ? bv : 0.f);

    float prm = fmaf(ub0, cmb[0], fmaf(ui[0], cma[0], etm[0] * F0));
    float pri = fmaf(ub0, cib[0], fmaf(ui[0], cia[0], eti[0] * F0));
    vm[0] = RESC ? prm * em[0] * rz : prm * em[0];
    vi[0] = RESC ? pri * ei[0] * rz : pri * ei[0];
    float F = fmaf(w_[0], Fexp, Sr[0]);
    #pragma unroll
    for (int q = 1; q < TE; q++) {
        prm = fmaf(um[q - 1], cmb[q], fmaf(ui[q], cma[q], etm[q] * F));
        pri = fmaf(um[q - 1], cib[q], fmaf(ui[q], cia[q], eti[q] * F));
        vm[q] = RESC ? prm * em[q] * rz : prm * em[q];
        vi[q] = RESC ? pri * ei[q] * rz : pri * ei[q];
        F = fmaf(w_[q], F, Sr[q]);
    }
    vx = 0.f;
    if (l63) {
        float prx = fmaf(et_x, F, fmaf(um[TE - 1], ci_xb, uxin * ci_xa));
        vx = RESC ? prx * e_x * rz : prx * e_x;
    }
    // publish boundary for next step (consumed after next step's barrier)
    if (lane == 31 && wid == 0) s_bnd[P ^ 1] = vm[TE - 1];
}

// ---------------- forward recursion: 2 warps, alpha in registers, 1 bar/step ----------------
__global__ void __launch_bounds__(NT) hmm_forward(const float* __restrict__ seq,
                                                  const float* __restrict__ lscale,
                                                  float* __restrict__ out)
{
    __shared__ float4 s_T[2];
    __shared__ float  s_bnd[2];
    __shared__ float  s_red[2];
    __shared__ int    s_let[LL];

    const int b = blockIdx.x, tid = threadIdx.x, lane = tid & 31, wid = tid >> 5;
    const int j0 = tid * TE;
    const bool l63 = (tid == NT - 1);

    for (int l = tid; l < LL; l += NT) {
        const float* row = seq + ((size_t)b * LL + l) * AA;
        int let = AA;
        #pragma unroll
        for (int a = 0; a < AA; a++)
            if (row[a] > 0.5f) let = a;
        s_let[l] = let * ESTR;
    }

    float w_[TE], cfa[TE], cfb[TE], cma[TE], cmb[TE], cia[TE], cib[TE], etm[TE], eti[TE];
    #pragma unroll
    for (int q = 0; q < TE; q++) {
        const int j = j0 + q;
        w_[q]  = g_w[j];
        cfa[q] = g_cf[MM + j];  cfb[q] = j ? g_cf[j - 1] : 0.f;
        cma[q] = g_cm[MM + j];  cmb[q] = j ? g_cm[j - 1] : 0.f;
        cia[q] = g_ci[MM + j];  cib[q] = j ? g_ci[j - 1] : 0.f;
        etm[q] = g_et[j];       eti[q] = g_et[MM + j];
    }
    const float kw1 = __fdividef(g_cf[191], g_w[192]);
    float et_x = 0.f, ci_xa = 0.f, ci_xb = 0.f;
    if (l63) { et_x = g_et[KK - 1]; ci_xa = g_ci[KK - 1]; ci_xb = g_ci[MM - 1]; }

    // constant-W scan multipliers (one dummy W-only scan)
    float WL[5], Wfin;
    {
        float Wv = ((w_[0] * w_[1]) * (w_[2] * w_[3])) * (w_[4] * w_[5]);
        #pragma unroll
        for (int k = 0; k < 5; k++) {
            const int o = 1 << k;
            WL[k] = Wv;
            float Wp = __shfl_up_sync(0xffffffffu, Wv, o);
            if (lane >= o) Wv *= Wp;
        }
        Wfin = Wv;
    }
    const float Wexcl = __shfl_up_sync(0xffffffffu, Wfin, 1);

    __syncthreads();   // s_let visible

    // init: u0 = exp(init) * emission(t=0)
    float um[TE], ui[TE], ux = 0.f;
    {
        const float* ob = g_eobs + s_let[0];
        #pragma unroll
        for (int q = 0; q < TE; q++) {
            um[q] = g_einit[j0 + q]      * ob[j0 + q];
            ui[q] = g_einit[MM + j0 + q] * ob[MM + j0 + q];
        }
        if (l63) ux = g_einit[KK - 1] * ob[KK - 1];
        if (lane == 31 && wid == 0) s_bnd[0] = um[TE - 1];
    }
    __syncthreads();

    int pacc = 0;
    float vm[TE], vi[TE], vx;

    stepfn<true, 0>(um, ui, ux, vm, vi, vx, w_, cfa, cfb, cma, cmb, cia, cib, etm, eti,
                    WL, Wexcl, kw1, s_T, s_bnd, j0, lane, wid, l63,
                    et_x, ci_xa, ci_xb, g_eobs + s_let[1], pacc);
    for (int t = 2; t < LL; t += 2) {
        stepfn<true, 1>(vm, vi, vx, um, ui, ux, w_, cfa, cfb, cma, cmb, cia, cib, etm, eti,
                        WL, Wexcl, kw1, s_T, s_bnd, j0, lane, wid, l63,
                        et_x, ci_xa, ci_xb, g_eobs + s_let[t], pacc);
        stepfn<false, 0>(um, ui, ux, vm, vi, vx, w_, cfa, cfb, cma, cmb, cia, cib, etm, eti,
                         WL, Wexcl, kw1, s_T, s_bnd, j0, lane, wid, l63,
                         et_x, ci_xa, ci_xb, g_eobs + s_let[t + 1], pacc);
    }

    // final: log(sum u) + 2^pacc correction
    float ps = vx;
    #pragma unroll
    for (int q = 0; q < TE; q++) ps += vm[q] + vi[q];
    #pragma unroll
    for (int o = 16; o; o >>= 1) ps += __shfl_xor_sync(0xffffffffu, ps, o);
    if (lane == 0) s_red[wid] = ps;
    __syncthreads();
    if (tid == 0) {
        float Zt = s_red[0] + s_red[1];
        out[b] = lscale[0] * ((float)((double)pacc * 0.6931471805599453) + __logf(Zt));
    }
}

extern "C" void kernel_launch(void* const* d_in, const int* in_sizes, int n_in,
                              void* d_out, int out_size)
{
    const float* pre  = (const float*)d_in[0];
    const float* iseq = (const float*)d_in[1];
    const float* ins  = (const float*)d_in[2];
    const float* del  = (const float*)d_in[3];
    const float* seq  = (const float*)d_in[4];
    const float* ls   = (const float*)d_in[5];
    float* out = (float*)d_out;

    prep_kernel<<<1, 512>>>(ins, del);
    emis_kernel<<<7, 128>>>(pre, iseq);
    hmm_forward<<<BB, NT>>>(seq, ls, out);
}